// round 1
// baseline (speedup 1.0000x reference)
#include <cuda_runtime.h>
#include <cuda_bf16.h>
#include <cstdint>

// Problem constants
#define B_   4
#define T_   2048
#define D_   1024
#define H_   16
#define L_   64
#define BT_  (B_*T_)        // 8192
#define BH_  (B_*H_)        // 64
#define CHUNK 128
#define NC   (T_/CHUNK)     // 16

// Scratch (device globals; no allocation allowed)
__device__ float g_qkv[(size_t)BT_ * 3 * D_];   // (B*T, 3072)  q|k|v
__device__ float g_y  [(size_t)BT_ * D_];       // (B*T, 1024)
__device__ float g_Sc [(size_t)BH_ * NC * L_ * L_]; // per-chunk states -> exclusive prefix (in place)
__device__ float g_ks [(size_t)BH_ * NC * L_];      // per-chunk k sums -> exclusive prefix (in place)

// ---------------------------------------------------------------------------
// GEMM: C[M,N] = A[M,K] * op(B).  BT=true: B is (N,K) row-major (C=A*B^T).
//                                 BT=false: B is (K,N) row-major (C=A*B).
// 128x128 tile, BK=16, 256 threads, 8x8 per thread, fp32.
// ---------------------------------------------------------------------------
template<bool BTRANS>
__global__ void __launch_bounds__(256)
gemm128(const float* __restrict__ A, const float* __restrict__ B,
        float* __restrict__ C, int M, int N, int K)
{
    __shared__ float As[16][132];
    __shared__ float Bs[16][132];
    const int tid = threadIdx.x;
    const int m0 = blockIdx.y * 128;
    const int n0 = blockIdx.x * 128;
    const int arow = tid >> 2;          // 0..63
    const int akg  = (tid & 3) << 2;    // 0,4,8,12
    const int ty = tid >> 4, tx = tid & 15;

    float acc[8][8];
#pragma unroll
    for (int i = 0; i < 8; i++)
#pragma unroll
        for (int j = 0; j < 8; j++) acc[i][j] = 0.f;

    for (int k0 = 0; k0 < K; k0 += 16) {
        // A tile (M,K row-major) -> As[k][m]
#pragma unroll
        for (int r = 0; r < 2; r++) {
            float4 v = *(const float4*)&A[(size_t)(m0 + arow + r * 64) * K + k0 + akg];
            As[akg + 0][arow + r * 64] = v.x;
            As[akg + 1][arow + r * 64] = v.y;
            As[akg + 2][arow + r * 64] = v.z;
            As[akg + 3][arow + r * 64] = v.w;
        }
        if (BTRANS) {
            // B is (N,K): rows of B are K-contiguous
#pragma unroll
            for (int r = 0; r < 2; r++) {
                float4 v = *(const float4*)&B[(size_t)(n0 + arow + r * 64) * K + k0 + akg];
                Bs[akg + 0][arow + r * 64] = v.x;
                Bs[akg + 1][arow + r * 64] = v.y;
                Bs[akg + 2][arow + r * 64] = v.z;
                Bs[akg + 3][arow + r * 64] = v.w;
            }
        } else {
            // B is (K,N): rows are N-contiguous
            const int krow = tid >> 5;            // 0..7
            const int nc   = (tid & 31) << 2;     // 0..124
#pragma unroll
            for (int r = 0; r < 2; r++) {
                float4 v = *(const float4*)&B[(size_t)(k0 + krow + r * 8) * N + n0 + nc];
                *(float4*)&Bs[krow + r * 8][nc] = v;
            }
        }
        __syncthreads();
#pragma unroll
        for (int kk = 0; kk < 16; kk++) {
            float a[8], b[8];
            *(float4*)&a[0] = *(const float4*)&As[kk][ty * 8];
            *(float4*)&a[4] = *(const float4*)&As[kk][ty * 8 + 4];
            *(float4*)&b[0] = *(const float4*)&Bs[kk][tx * 8];
            *(float4*)&b[4] = *(const float4*)&Bs[kk][tx * 8 + 4];
#pragma unroll
            for (int i = 0; i < 8; i++)
#pragma unroll
                for (int j = 0; j < 8; j++) acc[i][j] += a[i] * b[j];
        }
        __syncthreads();
    }
#pragma unroll
    for (int i = 0; i < 8; i++) {
        float* cp = &C[(size_t)(m0 + ty * 8 + i) * N + n0 + tx * 8];
        *(float4*)cp     = make_float4(acc[i][0], acc[i][1], acc[i][2], acc[i][3]);
        *(float4*)(cp+4) = make_float4(acc[i][4], acc[i][5], acc[i][6], acc[i][7]);
    }
}

// ---------------------------------------------------------------------------
// Pointwise prep: per (b,t): q-part -> softmax(q*scale) over each head's 64;
// k-part -> exp(k*scale)+1e-6. In place on g_qkv.
// grid = 8192 blocks, 512 threads (warp h handles head h).
// ---------------------------------------------------------------------------
__global__ void prep_kernel(float* __restrict__ qkv)
{
    const size_t base = (size_t)blockIdx.x * (3 * D_);
    const int h = threadIdx.x >> 5;
    const int lane = threadIdx.x & 31;
    float* qp = qkv + base + h * L_;
    float* kp = qkv + base + D_ + h * L_;

    float q0 = qp[lane] * 0.125f;
    float q1 = qp[lane + 32] * 0.125f;
    float mx = fmaxf(q0, q1);
#pragma unroll
    for (int off = 16; off > 0; off >>= 1)
        mx = fmaxf(mx, __shfl_xor_sync(0xffffffffu, mx, off));
    float e0 = expf(q0 - mx), e1 = expf(q1 - mx);
    float s = e0 + e1;
#pragma unroll
    for (int off = 16; off > 0; off >>= 1)
        s += __shfl_xor_sync(0xffffffffu, s, off);
    float inv = 1.0f / s;
    qp[lane]      = e0 * inv;
    qp[lane + 32] = e1 * inv;

    float k0 = kp[lane], k1 = kp[lane + 32];
    kp[lane]      = expf(k0 * 0.125f) + 1e-6f;
    kp[lane + 32] = expf(k1 * 0.125f) + 1e-6f;
}

// ---------------------------------------------------------------------------
// Per-chunk state: S_c[l][m] = sum_{t in chunk} K[t][l]*V[t][m]; ksum_c[l].
// grid (NC, BH), 256 threads, 64KB dynamic smem.
// ---------------------------------------------------------------------------
__global__ void __launch_bounds__(256)
chunkstate_kernel(const float* __restrict__ qkv,
                  float* __restrict__ Sc, float* __restrict__ ks)
{
    extern __shared__ float sm[];
    float* Ks = sm;            // 128*64
    float* Vs = sm + CHUNK * L_;
    const int c = blockIdx.x, bh = blockIdx.y;
    const int b = bh >> 4, h = bh & 15;
    const size_t rowbase = ((size_t)(b * T_ + c * CHUNK)) * (3 * D_) + h * L_;

    for (int i = threadIdx.x; i < CHUNK * 16; i += 256) {
        int t = i >> 4, f = (i & 15) << 2;
        size_t g = rowbase + (size_t)t * (3 * D_) + f;
        *(float4*)&Ks[t * L_ + f] = *(const float4*)&qkv[g + D_];
        *(float4*)&Vs[t * L_ + f] = *(const float4*)&qkv[g + 2 * D_];
    }
    __syncthreads();

    const int l0 = (threadIdx.x >> 4) << 2;
    const int m0 = (threadIdx.x & 15) << 2;
    float acc[4][4];
#pragma unroll
    for (int i = 0; i < 4; i++)
#pragma unroll
        for (int j = 0; j < 4; j++) acc[i][j] = 0.f;
    for (int t = 0; t < CHUNK; t++) {
        float a[4], v[4];
#pragma unroll
        for (int i = 0; i < 4; i++) a[i] = Ks[t * L_ + l0 + i];
#pragma unroll
        for (int j = 0; j < 4; j++) v[j] = Vs[t * L_ + m0 + j];
#pragma unroll
        for (int i = 0; i < 4; i++)
#pragma unroll
            for (int j = 0; j < 4; j++) acc[i][j] += a[i] * v[j];
    }
    const size_t sbase = ((size_t)bh * NC + c) * (L_ * L_);
#pragma unroll
    for (int i = 0; i < 4; i++)
#pragma unroll
        for (int j = 0; j < 4; j++)
            Sc[sbase + (size_t)(l0 + i) * L_ + m0 + j] = acc[i][j];

    if (threadIdx.x < L_) {
        float s = 0.f;
        for (int t = 0; t < CHUNK; t++) s += Ks[t * L_ + threadIdx.x];
        ks[((size_t)bh * NC + c) * L_ + threadIdx.x] = s;
    }
}

// ---------------------------------------------------------------------------
// Exclusive prefix over chunks, in place. grid 64 blocks, 256 threads.
// ---------------------------------------------------------------------------
__global__ void prefix_kernel(float* __restrict__ Sc, float* __restrict__ ks)
{
    const int bh = blockIdx.x;
    const size_t base = (size_t)bh * NC * (L_ * L_);
    for (int e = threadIdx.x; e < L_ * L_; e += 256) {
        float acc = 0.f;
#pragma unroll
        for (int c = 0; c < NC; c++) {
            size_t idx = base + (size_t)c * (L_ * L_) + e;
            float tmp = Sc[idx];
            Sc[idx] = acc;
            acc += tmp;
        }
    }
    if (threadIdx.x < L_) {
        const size_t kb = (size_t)bh * NC * L_;
        float acc = 0.f;
#pragma unroll
        for (int c = 0; c < NC; c++) {
            size_t idx = kb + (size_t)c * L_ + threadIdx.x;
            float tmp = ks[idx];
            ks[idx] = acc;
            acc += tmp;
        }
    }
}

// ---------------------------------------------------------------------------
// Chunk attention: normalize qs by causal k-norm, then
// Y = qs @ S_prev + causal(qs @ K^T) @ V.
// grid (NC, BH), 128 threads (thread = row t), 112KB dynamic smem.
// ---------------------------------------------------------------------------
__global__ void __launch_bounds__(128)
attn_kernel(const float* __restrict__ qkv, const float* __restrict__ Sprev,
            const float* __restrict__ kpre, float* __restrict__ y)
{
    extern __shared__ float sm[];
    float* Qs = sm;                 // 128*64
    float* Ks = sm + 8192;          // 128*64
    float* Vs = sm + 16384;         // 128*64
    float* Sp = sm + 24576;         // 64*64
    const int c = blockIdx.x, bh = blockIdx.y;
    const int b = bh >> 4, h = bh & 15;
    const int tid = threadIdx.x;
    const size_t rowbase = ((size_t)(b * T_ + c * CHUNK)) * (3 * D_) + h * L_;

    for (int i = tid; i < CHUNK * 16; i += 128) {
        int t = i >> 4, f = (i & 15) << 2;
        size_t g = rowbase + (size_t)t * (3 * D_) + f;
        *(float4*)&Qs[t * L_ + f] = *(const float4*)&qkv[g];
        *(float4*)&Ks[t * L_ + f] = *(const float4*)&qkv[g + D_];
        *(float4*)&Vs[t * L_ + f] = *(const float4*)&qkv[g + 2 * D_];
    }
    const size_t sbase = ((size_t)bh * NC + c) * (L_ * L_);
    for (int i = tid; i < L_ * L_; i += 128) Sp[i] = Sprev[sbase + i];
    __syncthreads();

    // normalize: qs[t][l] = softmax_q[t][l] / (kpre[l] + cumsum_{s<=t} K[s][l])
    if (tid < L_) {
        float acc = kpre[((size_t)bh * NC + c) * L_ + tid];
        for (int t = 0; t < CHUNK; t++) {
            acc += Ks[t * L_ + tid];
            Qs[t * L_ + tid] /= acc;
        }
    }
    __syncthreads();

    const int t = tid;
    float q[L_];
#pragma unroll
    for (int l = 0; l < L_; l++) q[l] = Qs[t * L_ + l];

    float4 yv[16];
#pragma unroll
    for (int f = 0; f < 16; f++) yv[f] = make_float4(0.f, 0.f, 0.f, 0.f);

    // inter-chunk: qs @ S_prev  (broadcast smem reads)
#pragma unroll
    for (int l = 0; l < L_; l++) {
        float ql = q[l];
        const float4* sp = (const float4*)&Sp[l * L_];
#pragma unroll
        for (int f = 0; f < 16; f++) {
            float4 s = sp[f];
            yv[f].x += ql * s.x; yv[f].y += ql * s.y;
            yv[f].z += ql * s.z; yv[f].w += ql * s.w;
        }
    }

    // intra-chunk causal (inclusive)
    for (int s = 0; s <= t; s++) {
        const float4* kp = (const float4*)&Ks[s * L_];
        float a = 0.f;
#pragma unroll
        for (int lf = 0; lf < 16; lf++) {
            float4 kv = kp[lf];
            a += q[lf*4+0]*kv.x + q[lf*4+1]*kv.y + q[lf*4+2]*kv.z + q[lf*4+3]*kv.w;
        }
        const float4* vp = (const float4*)&Vs[s * L_];
#pragma unroll
        for (int f = 0; f < 16; f++) {
            float4 vv = vp[f];
            yv[f].x += a * vv.x; yv[f].y += a * vv.y;
            yv[f].z += a * vv.z; yv[f].w += a * vv.w;
        }
    }

    const size_t ybase = ((size_t)(b * T_ + c * CHUNK + t)) * D_ + h * L_;
#pragma unroll
    for (int f = 0; f < 16; f++) *(float4*)&y[ybase + f * 4] = yv[f];
}

// ---------------------------------------------------------------------------
extern "C" void kernel_launch(void* const* d_in, const int* in_sizes, int n_in,
                              void* d_out, int out_size)
{
    const float* x  = (const float*)d_in[0];   // (4,2048,1024)
    const float* w  = (const float*)d_in[1];   // (3072,1024)
    const float* wo = (const float*)d_in[2];   // (1024,1024)
    float* out = (float*)d_out;                // (4,2048,1024)

    float *qkv, *y, *Sc, *ks;
    cudaGetSymbolAddress((void**)&qkv, g_qkv);
    cudaGetSymbolAddress((void**)&y,   g_y);
    cudaGetSymbolAddress((void**)&Sc,  g_Sc);
    cudaGetSymbolAddress((void**)&ks,  g_ks);

    cudaFuncSetAttribute(chunkstate_kernel,
                         cudaFuncAttributeMaxDynamicSharedMemorySize, 65536);
    cudaFuncSetAttribute(attn_kernel,
                         cudaFuncAttributeMaxDynamicSharedMemorySize, 114688);

    // 1) qkv = x @ w^T           M=8192 N=3072 K=1024
    gemm128<true><<<dim3(3072/128, 8192/128), 256>>>(x, w, qkv, BT_, 3 * D_, D_);
    // 2) softmax(q), exp(k)+1e-6 in place
    prep_kernel<<<BT_, 512>>>(qkv);
    // 3) per-chunk states + k sums
    chunkstate_kernel<<<dim3(NC, BH_), 256, 65536>>>(qkv, Sc, ks);
    // 4) exclusive prefix over chunks
    prefix_kernel<<<BH_, 256>>>(Sc, ks);
    // 5) chunk attention -> y
    attn_kernel<<<dim3(NC, BH_), 128, 114688>>>(qkv, Sc, ks, y);
    // 6) out = y @ w_out         M=8192 N=1024 K=1024
    gemm128<false><<<dim3(1024/128, 8192/128), 256>>>(y, wo, out, BT_, D_, D_);
}

// round 3
// speedup vs baseline: 2.1665x; 2.1665x over previous
#include <cuda_runtime.h>
#include <cuda_bf16.h>
#include <cstdint>

// Problem constants
#define B_   4
#define T_   2048
#define D_   1024
#define H_   16
#define L_   64
#define BT_  (B_*T_)        // 8192
#define BH_  (B_*H_)        // 64
#define CHUNK 128
#define NC   (T_/CHUNK)     // 16

// ---------------------------------------------------------------------------
// Scratch (device globals; no allocation allowed)
// ---------------------------------------------------------------------------
__device__ float g_qkv[(size_t)BT_ * 3 * D_];        // (8192, 3072)  q|k|v fp32
__device__ float g_Sc [(size_t)BH_ * NC * L_ * L_];  // chunk states -> excl prefix
__device__ float g_ks [(size_t)BH_ * NC * L_];       // chunk k-sums -> excl prefix
__device__ __nv_bfloat16 g_xhi[(size_t)BT_ * D_];
__device__ __nv_bfloat16 g_xlo[(size_t)BT_ * D_];
__device__ __nv_bfloat16 g_whi[(size_t)3 * D_ * D_];
__device__ __nv_bfloat16 g_wlo[(size_t)3 * D_ * D_];
__device__ __nv_bfloat16 g_wothi[(size_t)D_ * D_];   // w_out^T
__device__ __nv_bfloat16 g_wotlo[(size_t)D_ * D_];
__device__ __nv_bfloat16 g_yhi[(size_t)BT_ * D_];
__device__ __nv_bfloat16 g_ylo[(size_t)BT_ * D_];

// ---------------------------------------------------------------------------
// PTX helpers (baseline sm_80+ instructions only — harness targets plain sm_103)
// ---------------------------------------------------------------------------
__device__ __forceinline__ uint32_t smem_u32(const void* p) {
    uint32_t a;
    asm("{ .reg .u64 t; cvta.to.shared.u64 t, %1; cvt.u32.u64 %0, t; }" : "=r"(a) : "l"(p));
    return a;
}

__device__ __forceinline__ void cp_async16(uint32_t dst, const void* src) {
    asm volatile("cp.async.cg.shared.global [%0], [%1], 16;" :: "r"(dst), "l"(src) : "memory");
}
__device__ __forceinline__ void cp_commit() {
    asm volatile("cp.async.commit_group;" ::: "memory");
}
__device__ __forceinline__ void cp_wait1() {
    asm volatile("cp.async.wait_group 1;" ::: "memory");
}

__device__ __forceinline__ void ldsm_x4(uint32_t addr, uint32_t& r0, uint32_t& r1,
                                        uint32_t& r2, uint32_t& r3) {
    asm volatile("ldmatrix.sync.aligned.m8n8.x4.shared.b16 {%0,%1,%2,%3}, [%4];"
                 : "=r"(r0), "=r"(r1), "=r"(r2), "=r"(r3) : "r"(addr));
}

__device__ __forceinline__ void mma_bf16(float* c, const uint32_t* a, const uint32_t* b) {
    asm volatile(
        "mma.sync.aligned.m16n8k16.row.col.f32.bf16.bf16.f32 "
        "{%0,%1,%2,%3}, {%4,%5,%6,%7}, {%8,%9}, {%0,%1,%2,%3};"
        : "+f"(c[0]), "+f"(c[1]), "+f"(c[2]), "+f"(c[3])
        : "r"(a[0]), "r"(a[1]), "r"(a[2]), "r"(a[3]), "r"(b[0]), "r"(b[1]));
}

// ---------------------------------------------------------------------------
// Split fp32 -> bf16 hi/lo (vectorized)
// ---------------------------------------------------------------------------
__global__ void split_kernel(const float* __restrict__ src,
                             __nv_bfloat16* __restrict__ hi,
                             __nv_bfloat16* __restrict__ lo, int n4)
{
    int i = blockIdx.x * blockDim.x + threadIdx.x;
    if (i >= n4) return;
    float4 v = ((const float4*)src)[i];
    __nv_bfloat16 h0 = __float2bfloat16(v.x), h1 = __float2bfloat16(v.y);
    __nv_bfloat16 h2 = __float2bfloat16(v.z), h3 = __float2bfloat16(v.w);
    __nv_bfloat16 l0 = __float2bfloat16(v.x - __bfloat162float(h0));
    __nv_bfloat16 l1 = __float2bfloat16(v.y - __bfloat162float(h1));
    __nv_bfloat16 l2 = __float2bfloat16(v.z - __bfloat162float(h2));
    __nv_bfloat16 l3 = __float2bfloat16(v.w - __bfloat162float(h3));
    ((__nv_bfloat162*)hi)[2 * i]     = __halves2bfloat162(h0, h1);
    ((__nv_bfloat162*)hi)[2 * i + 1] = __halves2bfloat162(h2, h3);
    ((__nv_bfloat162*)lo)[2 * i]     = __halves2bfloat162(l0, l1);
    ((__nv_bfloat162*)lo)[2 * i + 1] = __halves2bfloat162(l2, l3);
}

// Transpose + split w_out (1024x1024): dst[n][k] = split(src[k][n])
__global__ void split_transpose_kernel(const float* __restrict__ src,
                                       __nv_bfloat16* __restrict__ hi,
                                       __nv_bfloat16* __restrict__ lo)
{
    __shared__ float tile[32][33];
    int n0 = blockIdx.x * 32, k0 = blockIdx.y * 32;
    int tx = threadIdx.x, ty = threadIdx.y;
    for (int r = ty; r < 32; r += 8)
        tile[r][tx] = src[(size_t)(k0 + r) * D_ + n0 + tx];
    __syncthreads();
    for (int r = ty; r < 32; r += 8) {
        float v = tile[tx][r];   // src[k0+tx][n0+r] -> dst[n0+r][k0+tx]
        __nv_bfloat16 h = __float2bfloat16(v);
        size_t idx = (size_t)(n0 + r) * D_ + k0 + tx;
        hi[idx] = h;
        lo[idx] = __float2bfloat16(v - __bfloat162float(h));
    }
}

// ---------------------------------------------------------------------------
// HMMA bf16 split GEMM: C[M,N] = A*B^T fp32 via 3-term bf16 split.
// A (M,K) hi/lo row-major; B (N,K) hi/lo row-major.
// 128x128 block tile, BK=64, 256 threads (8 warps, 4x2), warp tile 32x64.
// cp.async double-buffered; SW-xor swizzle; ldmatrix.x4 for both operands.
// ---------------------------------------------------------------------------
#define GT_TILE_BYTES  16384           // 128 rows x 128B (64 bf16)
#define GT_STAGE_BYTES (4 * GT_TILE_BYTES)   // Ahi, Alo, Bhi, Blo
#define GT_SMEM_TOTAL  (2 * GT_STAGE_BYTES)  // 131072

__global__ void __launch_bounds__(256, 1)
gemm_mma(const __nv_bfloat16* __restrict__ Ahi, const __nv_bfloat16* __restrict__ Alo,
         const __nv_bfloat16* __restrict__ Bhi, const __nv_bfloat16* __restrict__ Blo,
         float* __restrict__ C, int N, int K)
{
    extern __shared__ char smem[];
    const uint32_t smem_base = smem_u32(smem);
    const int tid = threadIdx.x;
    const int wid = tid >> 5, lane = tid & 31;
    const int m0 = blockIdx.y * 128, n0 = blockIdx.x * 128;
    const int wm = (wid & 3) * 32;          // warp row offset within tile
    const int wn = (wid >> 2) * 64;         // warp col offset within tile

    const __nv_bfloat16* srcs[4] = { Ahi, Alo, Bhi, Blo };

    // per-thread load slots: 16 chunks of 16B per stage (4 per tile)
    // chunk j (0..1023) of a tile: r=j>>3, c=j&7 ; swizzled dst r*128 + (c^(r&7))*16
    auto load_stage = [&](int kt, int s) {
        const int k0 = kt << 6;
#pragma unroll
        for (int tI = 0; tI < 4; tI++) {
            const __nv_bfloat16* src = srcs[tI];
            const int rb = (tI < 2) ? m0 : n0;
            const uint32_t tb = smem_base + s * GT_STAGE_BYTES + tI * GT_TILE_BYTES;
#pragma unroll
            for (int ii = 0; ii < 4; ii++) {
                int j = tid + ii * 256;
                int r = j >> 3, c = j & 7;
                const void* g = &src[(size_t)(rb + r) * K + k0 + c * 8];
                uint32_t d = tb + (uint32_t)(r * 128 + ((c ^ (r & 7)) << 4));
                cp_async16(d, g);
            }
        }
    };

    float acc[2][8][4];
#pragma unroll
    for (int mt = 0; mt < 2; mt++)
#pragma unroll
        for (int nt = 0; nt < 8; nt++)
#pragma unroll
            for (int e = 0; e < 4; e++) acc[mt][nt][e] = 0.f;

    const int NKT = K >> 6;   // 16
    load_stage(0, 0); cp_commit();
    load_stage(1, 1); cp_commit();

    // ldmatrix lane addressing (constant across kk except chunk)
    const int a_row = (lane & 15);          // row within 16-row tile
    const int a_khalf = lane >> 4;          // 0/1 -> 16B chunk parity
    const int b_grp = (lane >> 4) & 1;      // n8 group within pair
    const int b_khalf = (lane >> 3) & 1;
    const int b_row = lane & 7;

    for (int kt = 0; kt < NKT; kt++) {
        const int s = kt & 1;
        const uint32_t st = smem_base + s * GT_STAGE_BYTES;
        cp_wait1();
        __syncthreads();

        const uint32_t aAhi = st;
        const uint32_t aBhi = st + 2 * GT_TILE_BYTES;

#pragma unroll
        for (int kk = 0; kk < 4; kk++) {
            uint32_t ah[2][4], al[2][4];
#pragma unroll
            for (int mt = 0; mt < 2; mt++) {
                int row = wm + mt * 16 + a_row;
                int chunk = 2 * kk + a_khalf;
                uint32_t off = (uint32_t)(row * 128 + ((chunk ^ (row & 7)) << 4));
                ldsm_x4(aAhi + off, ah[mt][0], ah[mt][1], ah[mt][2], ah[mt][3]);
                ldsm_x4(aAhi + GT_TILE_BYTES + off, al[mt][0], al[mt][1], al[mt][2], al[mt][3]);
            }
            uint32_t bh[4][4], bl[4][4];
#pragma unroll
            for (int np = 0; np < 4; np++) {
                int row = wn + np * 16 + b_grp * 8 + b_row;
                int chunk = 2 * kk + b_khalf;
                uint32_t off = (uint32_t)(row * 128 + ((chunk ^ (row & 7)) << 4));
                ldsm_x4(aBhi + off, bh[np][0], bh[np][1], bh[np][2], bh[np][3]);
                ldsm_x4(aBhi + GT_TILE_BYTES + off, bl[np][0], bl[np][1], bl[np][2], bl[np][3]);
            }
#pragma unroll
            for (int mt = 0; mt < 2; mt++)
#pragma unroll
                for (int nt = 0; nt < 8; nt++) {
                    const uint32_t* bhf = &bh[nt >> 1][(nt & 1) * 2];
                    const uint32_t* blf = &bl[nt >> 1][(nt & 1) * 2];
                    mma_bf16(acc[mt][nt], ah[mt], bhf);   // hi*hi
                    mma_bf16(acc[mt][nt], ah[mt], blf);   // hi*lo
                    mma_bf16(acc[mt][nt], al[mt], bhf);   // lo*hi
                }
        }
        __syncthreads();
        if (kt + 2 < NKT) load_stage(kt + 2, s);
        cp_commit();
    }

    // Epilogue: c0,c1 -> (row g, cols 2tig,2tig+1); c2,c3 -> row g+8
    const int g = lane >> 2, tig = lane & 3;
#pragma unroll
    for (int mt = 0; mt < 2; mt++) {
        int row = m0 + wm + mt * 16 + g;
#pragma unroll
        for (int nt = 0; nt < 8; nt++) {
            int col = n0 + wn + nt * 8 + 2 * tig;
            float* c = acc[mt][nt];
            *(float2*)&C[(size_t)row * N + col]       = make_float2(c[0], c[1]);
            *(float2*)&C[(size_t)(row + 8) * N + col] = make_float2(c[2], c[3]);
        }
    }
}

// ---------------------------------------------------------------------------
// Pointwise prep: softmax(q*scale) per head, exp(k*scale)+1e-6, in place.
// ---------------------------------------------------------------------------
__global__ void prep_kernel(float* __restrict__ qkv)
{
    const size_t base = (size_t)blockIdx.x * (3 * D_);
    const int h = threadIdx.x >> 5;
    const int lane = threadIdx.x & 31;
    float* qp = qkv + base + h * L_;
    float* kp = qkv + base + D_ + h * L_;

    float q0 = qp[lane] * 0.125f;
    float q1 = qp[lane + 32] * 0.125f;
    float mx = fmaxf(q0, q1);
#pragma unroll
    for (int off = 16; off > 0; off >>= 1)
        mx = fmaxf(mx, __shfl_xor_sync(0xffffffffu, mx, off));
    float e0 = expf(q0 - mx), e1 = expf(q1 - mx);
    float s = e0 + e1;
#pragma unroll
    for (int off = 16; off > 0; off >>= 1)
        s += __shfl_xor_sync(0xffffffffu, s, off);
    float inv = 1.0f / s;
    qp[lane]      = e0 * inv;
    qp[lane + 32] = e1 * inv;

    float k0 = kp[lane], k1 = kp[lane + 32];
    kp[lane]      = expf(k0 * 0.125f) + 1e-6f;
    kp[lane + 32] = expf(k1 * 0.125f) + 1e-6f;
}

// ---------------------------------------------------------------------------
// Per-chunk state: S_c[l][m] = sum_t K[t][l]*V[t][m]; ksum_c[l].
// ---------------------------------------------------------------------------
__global__ void __launch_bounds__(256)
chunkstate_kernel(const float* __restrict__ qkv,
                  float* __restrict__ Sc, float* __restrict__ ks)
{
    extern __shared__ float sm[];
    float* Ks = sm;
    float* Vs = sm + CHUNK * L_;
    const int c = blockIdx.x, bh = blockIdx.y;
    const int b = bh >> 4, h = bh & 15;
    const size_t rowbase = ((size_t)(b * T_ + c * CHUNK)) * (3 * D_) + h * L_;

    for (int i = threadIdx.x; i < CHUNK * 16; i += 256) {
        int t = i >> 4, f = (i & 15) << 2;
        size_t g = rowbase + (size_t)t * (3 * D_) + f;
        *(float4*)&Ks[t * L_ + f] = *(const float4*)&qkv[g + D_];
        *(float4*)&Vs[t * L_ + f] = *(const float4*)&qkv[g + 2 * D_];
    }
    __syncthreads();

    const int l0 = (threadIdx.x >> 4) << 2;
    const int m0 = (threadIdx.x & 15) << 2;
    float acc[4][4];
#pragma unroll
    for (int i = 0; i < 4; i++)
#pragma unroll
        for (int j = 0; j < 4; j++) acc[i][j] = 0.f;
    for (int t = 0; t < CHUNK; t++) {
        float a[4], v[4];
#pragma unroll
        for (int i = 0; i < 4; i++) a[i] = Ks[t * L_ + l0 + i];
#pragma unroll
        for (int j = 0; j < 4; j++) v[j] = Vs[t * L_ + m0 + j];
#pragma unroll
        for (int i = 0; i < 4; i++)
#pragma unroll
            for (int j = 0; j < 4; j++) acc[i][j] += a[i] * v[j];
    }
    const size_t sbase = ((size_t)bh * NC + c) * (L_ * L_);
#pragma unroll
    for (int i = 0; i < 4; i++)
#pragma unroll
        for (int j = 0; j < 4; j++)
            Sc[sbase + (size_t)(l0 + i) * L_ + m0 + j] = acc[i][j];

    if (threadIdx.x < L_) {
        float s = 0.f;
        for (int t = 0; t < CHUNK; t++) s += Ks[t * L_ + threadIdx.x];
        ks[((size_t)bh * NC + c) * L_ + threadIdx.x] = s;
    }
}

// ---------------------------------------------------------------------------
// Exclusive prefix over chunks, in place. grid (BH, 16) x 256.
// ---------------------------------------------------------------------------
__global__ void prefix_kernel(float* __restrict__ Sc, float* __restrict__ ks)
{
    const int bh = blockIdx.x;
    const int e = blockIdx.y * 256 + threadIdx.x;   // 0..4095
    const size_t base = (size_t)bh * NC * (L_ * L_);
    {
        float acc = 0.f;
#pragma unroll
        for (int c = 0; c < NC; c++) {
            size_t idx = base + (size_t)c * (L_ * L_) + e;
            float tmp = Sc[idx];
            Sc[idx] = acc;
            acc += tmp;
        }
    }
    if (blockIdx.y == 0 && threadIdx.x < L_) {
        const size_t kb = (size_t)bh * NC * L_;
        float acc = 0.f;
#pragma unroll
        for (int c = 0; c < NC; c++) {
            size_t idx = kb + (size_t)c * L_ + threadIdx.x;
            float tmp = ks[idx];
            ks[idx] = acc;
            acc += tmp;
        }
    }
}

// ---------------------------------------------------------------------------
// Chunk attention: Y = qs @ S_prev + causal(qs @ K^T) @ V, written bf16 hi/lo.
// ---------------------------------------------------------------------------
__global__ void __launch_bounds__(128)
attn_kernel(const float* __restrict__ qkv, const float* __restrict__ Sprev,
            const float* __restrict__ kpre,
            __nv_bfloat16* __restrict__ yhi, __nv_bfloat16* __restrict__ ylo)
{
    extern __shared__ float sm[];
    float* Qs = sm;                 // 128*64
    float* Ks = sm + 8192;          // 128*64
    float* Vs = sm + 16384;         // 128*64
    float* Sp = sm + 24576;         // 64*64
    const int c = blockIdx.x, bh = blockIdx.y;
    const int b = bh >> 4, h = bh & 15;
    const int tid = threadIdx.x;
    const size_t rowbase = ((size_t)(b * T_ + c * CHUNK)) * (3 * D_) + h * L_;

    for (int i = tid; i < CHUNK * 16; i += 128) {
        int t = i >> 4, f = (i & 15) << 2;
        size_t g = rowbase + (size_t)t * (3 * D_) + f;
        *(float4*)&Qs[t * L_ + f] = *(const float4*)&qkv[g];
        *(float4*)&Ks[t * L_ + f] = *(const float4*)&qkv[g + D_];
        *(float4*)&Vs[t * L_ + f] = *(const float4*)&qkv[g + 2 * D_];
    }
    const size_t sbase = ((size_t)bh * NC + c) * (L_ * L_);
    for (int i = tid; i < L_ * L_; i += 128) Sp[i] = Sprev[sbase + i];
    __syncthreads();

    if (tid < L_) {
        float acc = kpre[((size_t)bh * NC + c) * L_ + tid];
        for (int t = 0; t < CHUNK; t++) {
            acc += Ks[t * L_ + tid];
            Qs[t * L_ + tid] /= acc;
        }
    }
    __syncthreads();

    const int t = tid;
    float q[L_];
#pragma unroll
    for (int l = 0; l < L_; l++) q[l] = Qs[t * L_ + l];

    float4 yv[16];
#pragma unroll
    for (int f = 0; f < 16; f++) yv[f] = make_float4(0.f, 0.f, 0.f, 0.f);

    // inter-chunk: qs @ S_prev
#pragma unroll
    for (int l = 0; l < L_; l++) {
        float ql = q[l];
        const float4* sp = (const float4*)&Sp[l * L_];
#pragma unroll
        for (int f = 0; f < 16; f++) {
            float4 s = sp[f];
            yv[f].x += ql * s.x; yv[f].y += ql * s.y;
            yv[f].z += ql * s.z; yv[f].w += ql * s.w;
        }
    }

    // intra-chunk causal (inclusive)
    for (int s = 0; s <= t; s++) {
        const float4* kp = (const float4*)&Ks[s * L_];
        float a = 0.f;
#pragma unroll
        for (int lf = 0; lf < 16; lf++) {
            float4 kv = kp[lf];
            a += q[lf*4+0]*kv.x + q[lf*4+1]*kv.y + q[lf*4+2]*kv.z + q[lf*4+3]*kv.w;
        }
        const float4* vp = (const float4*)&Vs[s * L_];
#pragma unroll
        for (int f = 0; f < 16; f++) {
            float4 vv = vp[f];
            yv[f].x += a * vv.x; yv[f].y += a * vv.y;
            yv[f].z += a * vv.z; yv[f].w += a * vv.w;
        }
    }

    const size_t ybase = ((size_t)(b * T_ + c * CHUNK + t)) * D_ + h * L_;
#pragma unroll
    for (int f = 0; f < 16; f++) {
        float4 v = yv[f];
        __nv_bfloat16 h0 = __float2bfloat16(v.x), h1 = __float2bfloat16(v.y);
        __nv_bfloat16 h2 = __float2bfloat16(v.z), h3 = __float2bfloat16(v.w);
        __nv_bfloat16 l0 = __float2bfloat16(v.x - __bfloat162float(h0));
        __nv_bfloat16 l1 = __float2bfloat16(v.y - __bfloat162float(h1));
        __nv_bfloat16 l2 = __float2bfloat16(v.z - __bfloat162float(h2));
        __nv_bfloat16 l3 = __float2bfloat16(v.w - __bfloat162float(h3));
        __nv_bfloat162* ph = (__nv_bfloat162*)&yhi[ybase + f * 4];
        __nv_bfloat162* pl = (__nv_bfloat162*)&ylo[ybase + f * 4];
        ph[0] = __halves2bfloat162(h0, h1); ph[1] = __halves2bfloat162(h2, h3);
        pl[0] = __halves2bfloat162(l0, l1); pl[1] = __halves2bfloat162(l2, l3);
    }
}

// ---------------------------------------------------------------------------
extern "C" void kernel_launch(void* const* d_in, const int* in_sizes, int n_in,
                              void* d_out, int out_size)
{
    const float* x  = (const float*)d_in[0];   // (4,2048,1024)
    const float* w  = (const float*)d_in[1];   // (3072,1024)
    const float* wo = (const float*)d_in[2];   // (1024,1024)
    float* out = (float*)d_out;                // (4,2048,1024)

    float *qkv, *Sc, *ks;
    __nv_bfloat16 *xhi, *xlo, *whi, *wlo, *wothi, *wotlo, *yhi, *ylo;
    cudaGetSymbolAddress((void**)&qkv, g_qkv);
    cudaGetSymbolAddress((void**)&Sc,  g_Sc);
    cudaGetSymbolAddress((void**)&ks,  g_ks);
    cudaGetSymbolAddress((void**)&xhi, g_xhi);
    cudaGetSymbolAddress((void**)&xlo, g_xlo);
    cudaGetSymbolAddress((void**)&whi, g_whi);
    cudaGetSymbolAddress((void**)&wlo, g_wlo);
    cudaGetSymbolAddress((void**)&wothi, g_wothi);
    cudaGetSymbolAddress((void**)&wotlo, g_wotlo);
    cudaGetSymbolAddress((void**)&yhi, g_yhi);
    cudaGetSymbolAddress((void**)&ylo, g_ylo);

    cudaFuncSetAttribute(gemm_mma,
                         cudaFuncAttributeMaxDynamicSharedMemorySize, GT_SMEM_TOTAL);
    cudaFuncSetAttribute(chunkstate_kernel,
                         cudaFuncAttributeMaxDynamicSharedMemorySize, 65536);
    cudaFuncSetAttribute(attn_kernel,
                         cudaFuncAttributeMaxDynamicSharedMemorySize, 114688);

    // 0) split inputs into bf16 hi/lo
    split_kernel<<<(BT_ * D_ / 4 + 255) / 256, 256>>>(x, xhi, xlo, BT_ * D_ / 4);
    split_kernel<<<(3 * D_ * D_ / 4 + 255) / 256, 256>>>(w, whi, wlo, 3 * D_ * D_ / 4);
    split_transpose_kernel<<<dim3(D_ / 32, D_ / 32), dim3(32, 8)>>>(wo, wothi, wotlo);

    // 1) qkv = x @ w^T   (M=8192, N=3072, K=1024) on tensor cores (HMMA)
    gemm_mma<<<dim3(3 * D_ / 128, BT_ / 128), 256, GT_SMEM_TOTAL>>>(
        xhi, xlo, whi, wlo, qkv, 3 * D_, D_);
    // 2) softmax(q), exp(k)+1e-6 in place
    prep_kernel<<<BT_, 512>>>(qkv);
    // 3) per-chunk states + k sums
    chunkstate_kernel<<<dim3(NC, BH_), 256, 65536>>>(qkv, Sc, ks);
    // 4) exclusive prefix over chunks
    prefix_kernel<<<dim3(BH_, 16), 256>>>(Sc, ks);
    // 5) chunk attention -> y (bf16 split)
    attn_kernel<<<dim3(NC, BH_), 128, 114688>>>(qkv, Sc, ks, yhi, ylo);
    // 6) out = y @ w_out  (M=8192, N=1024, K=1024), B = w_out^T pre-split
    gemm_mma<<<dim3(D_ / 128, BT_ / 128), 256, GT_SMEM_TOTAL>>>(
        yhi, ylo, wothi, wotlo, out, D_, D_);
}